// round 3
// baseline (speedup 1.0000x reference)
#include <cuda_runtime.h>

#define BB 4
#define NT 4096
#define CC 256
#define II 128
#define NCH 64          // chunks per batch for suffix scan
#define CH  64          // rows per chunk (NCH*CH == NT)
#define BN_EPS 1e-3f

// ---------------- scratch (static device allocations; no cudaMalloc) -----------
__device__ float g_scr[BB*NT*II];          // g_x = x@wg + bg
__device__ float st_scr[BB*NT];            // s_theta per row
__device__ float sp_scr[BB*NT];            // s_phi per row
__device__ float keys_scr[BB*NT];          // sorted s_theta
__device__ int   perm_scr[BB*NT];          // sort permutation
__device__ float S1_scr[BB*(NT+1)*II];     // suffix sums of g (sorted order)
__device__ float S2_scr[BB*(NT+1)*II];     // suffix sums of s_theta*g
__device__ float c1_scr[BB*NCH*II];        // per-chunk sums
__device__ float c2_scr[BB*NCH*II];
__device__ float e1_scr[BB*NCH*II];        // exclusive suffix of chunk sums
__device__ float e2_scr[BB*NCH*II];
__device__ float ypre_scr[BB*NT*II];       // y before trailing conv
__device__ float vproj_scr[2*CC+2];        // wt@wc1, wp@wc2, ct, cp

// ---------------- 1. collapse score projections --------------------------------
__global__ __launch_bounds__(256) void prep_kernel(
        const float* __restrict__ wt, const float* __restrict__ bt,
        const float* __restrict__ wp, const float* __restrict__ bp,
        const float* __restrict__ wc) {
    int c = threadIdx.x;                    // 256 threads
    float vt = 0.f, vp = 0.f;
    #pragma unroll 4
    for (int k = 0; k < II; k++) {
        vt += wt[c*II + k] * wc[k];
        vp += wp[c*II + k] * wc[II + k];
    }
    vproj_scr[c]      = vt;
    vproj_scr[CC + c] = vp;
    if (c == 0) {
        float ct = 0.f, cp = 0.f;
        for (int k = 0; k < II; k++) { ct += bt[k]*wc[k]; cp += bp[k]*wc[II+k]; }
        vproj_scr[2*CC]   = ct;
        vproj_scr[2*CC+1] = cp;
    }
}

// ---------------- 2. per-row scalar scores --------------------------------------
__global__ __launch_bounds__(256) void scores_kernel(const float* __restrict__ x) {
    int warp = threadIdx.x >> 5, lane = threadIdx.x & 31;
    int m = blockIdx.x * 8 + warp;          // 8 warps/block, warp per row
    const float* xr = x + (size_t)m * CC;
    float at = 0.f, ap = 0.f;
    #pragma unroll
    for (int i = lane; i < CC; i += 32) {
        float xv = xr[i];
        at += xv * vproj_scr[i];
        ap += xv * vproj_scr[CC + i];
    }
    #pragma unroll
    for (int o = 16; o; o >>= 1) {
        at += __shfl_xor_sync(0xffffffffu, at, o);
        ap += __shfl_xor_sync(0xffffffffu, ap, o);
    }
    if (lane == 0) {
        st_scr[m] = at + vproj_scr[2*CC];
        sp_scr[m] = ap + vproj_scr[2*CC+1];
    }
}

// ---------------- 3. g_x = x @ wg + bg  (M=16384, K=256, N=128) -----------------
__global__ __launch_bounds__(256) void proj_gemm_kernel(
        const float* __restrict__ x, const float* __restrict__ wg,
        const float* __restrict__ bg) {
    __shared__ float as[16][128];
    __shared__ float bs[16][128];
    int m0 = blockIdx.x * 128;
    int tid = threadIdx.x;
    int tx = tid & 15, ty = tid >> 4;       // 16x16 thread grid, 8x8 microtile
    float acc[8][8] = {};
    for (int k0 = 0; k0 < CC; k0 += 16) {
        #pragma unroll
        for (int i = 0; i < 2; i++) {       // A: 128 rows x 16 k
            int id = tid + i*256;
            int row = id >> 2, c4 = id & 3;
            float4 v = *(const float4*)(x + (size_t)(m0+row)*CC + k0 + c4*4);
            as[c4*4+0][row] = v.x; as[c4*4+1][row] = v.y;
            as[c4*4+2][row] = v.z; as[c4*4+3][row] = v.w;
        }
        #pragma unroll
        for (int i = 0; i < 2; i++) {       // B: 16 k x 128 n
            int id = tid + i*256;
            int kr = id >> 5, c4 = id & 31;
            *(float4*)&bs[kr][c4*4] = *(const float4*)(wg + (size_t)(k0+kr)*II + c4*4);
        }
        __syncthreads();
        #pragma unroll
        for (int kk = 0; kk < 16; kk++) {
            float ar[8], br[8];
            *(float4*)(ar)   = *(float4*)&as[kk][ty*8];
            *(float4*)(ar+4) = *(float4*)&as[kk][ty*8+4];
            *(float4*)(br)   = *(float4*)&bs[kk][tx*8];
            *(float4*)(br+4) = *(float4*)&bs[kk][tx*8+4];
            #pragma unroll
            for (int i = 0; i < 8; i++)
                #pragma unroll
                for (int j = 0; j < 8; j++)
                    acc[i][j] += ar[i] * br[j];
        }
        __syncthreads();
    }
    #pragma unroll
    for (int i = 0; i < 8; i++) {
        int row = m0 + ty*8 + i;
        float4 o0, o1;
        o0.x = acc[i][0] + bg[tx*8+0]; o0.y = acc[i][1] + bg[tx*8+1];
        o0.z = acc[i][2] + bg[tx*8+2]; o0.w = acc[i][3] + bg[tx*8+3];
        o1.x = acc[i][4] + bg[tx*8+4]; o1.y = acc[i][5] + bg[tx*8+5];
        o1.z = acc[i][6] + bg[tx*8+6]; o1.w = acc[i][7] + bg[tx*8+7];
        *(float4*)&g_scr[(size_t)row*II + tx*8]     = o0;
        *(float4*)&g_scr[(size_t)row*II + tx*8 + 4] = o1;
    }
}

// ---------------- 4. per-batch bitonic sort of s_theta (with payload) -----------
__global__ __launch_bounds__(1024) void sort_kernel() {
    __shared__ float k_sm[NT];
    __shared__ int   i_sm[NT];
    int b = blockIdx.x, tid = threadIdx.x;
    for (int i = tid; i < NT; i += 1024) { k_sm[i] = st_scr[b*NT + i]; i_sm[i] = i; }
    __syncthreads();
    for (int k = 2; k <= NT; k <<= 1) {
        for (int j = k >> 1; j > 0; j >>= 1) {
            for (int t = tid; t < NT; t += 1024) {
                int ixj = t ^ j;
                if (ixj > t) {
                    bool up = ((t & k) == 0);
                    float a = k_sm[t], c = k_sm[ixj];
                    if ((a > c) == up) {
                        k_sm[t] = c; k_sm[ixj] = a;
                        int ia = i_sm[t]; i_sm[t] = i_sm[ixj]; i_sm[ixj] = ia;
                    }
                }
            }
            __syncthreads();
        }
    }
    for (int i = tid; i < NT; i += 1024) {
        keys_scr[b*NT + i] = k_sm[i];
        perm_scr[b*NT + i] = i_sm[i];
    }
}

// ---------------- 5. chunk sums (reduction, high MLP) ---------------------------
__global__ __launch_bounds__(128) void chunk_reduce_kernel() {
    __shared__ int   perm_sm[CH];
    __shared__ float keys_sm[CH];
    int b = blockIdx.x / NCH, c = blockIdx.x % NCH;
    int tid = threadIdx.x;
    int base = b*NT + c*CH;
    if (tid < CH) { perm_sm[tid] = perm_scr[base + tid]; keys_sm[tid] = keys_scr[base + tid]; }
    __syncthreads();
    float a1 = 0.f, a2 = 0.f;
    #pragma unroll 8
    for (int j = 0; j < CH; j++) {
        float g = g_scr[(size_t)(b*NT + perm_sm[j])*II + tid];
        a1 += g;
        a2 += keys_sm[j] * g;
    }
    c1_scr[(size_t)blockIdx.x*II + tid] = a1;
    c2_scr[(size_t)blockIdx.x*II + tid] = a2;
}

// ---------------- 6. exclusive suffix over chunk sums ---------------------------
__global__ __launch_bounds__(128) void chunk_suffix_kernel() {
    int b = blockIdx.x, d = threadIdx.x;
    float a1 = 0.f, a2 = 0.f;
    for (int c = NCH - 1; c >= 0; c--) {
        size_t idx = (size_t)(b*NCH + c)*II + d;
        e1_scr[idx] = a1; e2_scr[idx] = a2;
        a1 += c1_scr[idx]; a2 += c2_scr[idx];
    }
    S1_scr[(size_t)(b*(NT+1) + NT)*II + d] = 0.f;
    S2_scr[(size_t)(b*(NT+1) + NT)*II + d] = 0.f;
}

// ---------------- 7. fill suffix-sum tables -------------------------------------
__global__ __launch_bounds__(128) void scan_fill_kernel() {
    __shared__ float g_sm[CH][II];   // 32 KB
    __shared__ int   perm_sm[CH];
    __shared__ float keys_sm[CH];
    int b = blockIdx.x / NCH, c = blockIdx.x % NCH;
    int tid = threadIdx.x;
    int base = b*NT + c*CH;
    if (tid < CH) { perm_sm[tid] = perm_scr[base + tid]; keys_sm[tid] = keys_scr[base + tid]; }
    __syncthreads();
    #pragma unroll 4
    for (int t = 0; t < CH; t++)
        g_sm[t][tid] = g_scr[(size_t)(b*NT + perm_sm[t])*II + tid];
    __syncthreads();
    float a1 = e1_scr[(size_t)(b*NCH + c)*II + tid];
    float a2 = e2_scr[(size_t)(b*NCH + c)*II + tid];
    for (int j = CH - 1; j >= 0; j--) {
        float g = g_sm[j][tid];
        a1 += g;
        a2 += keys_sm[j] * g;
        int pos = c*CH + j;
        S1_scr[(size_t)(b*(NT+1) + pos)*II + tid] = a1;
        S2_scr[(size_t)(b*(NT+1) + pos)*II + tid] = a2;
    }
}

// ---------------- 8. y_pre via binary search + rank-1 combine -------------------
__global__ __launch_bounds__(128) void ypre_kernel() {
    __shared__ float keys_sm[NT];    // 16 KB
    int b = blockIdx.y, tid = threadIdx.x;
    for (int i = tid; i < NT; i += 128) keys_sm[i] = keys_scr[b*NT + i];
    __syncthreads();
    const float inv_n = 1.0f / (float)NT;
    for (int r = 0; r < 32; r++) {
        int row = blockIdx.x * 32 + r;
        int m = b*NT + row;
        float sp = sp_scr[m];
        float t = -sp;
        int lo = 0, hi = NT;
        #pragma unroll
        for (int it = 0; it < 12; it++) {   // covers range [0,4096]
            int mid = (lo + hi) >> 1;
            // mid can reach NT once lo==hi==NT; treat OOB as +inf (key > t)
            float kv = (mid < NT) ? keys_sm[mid] : __int_as_float(0x7f800000);
            if (kv > t) hi = mid; else lo = mid + 1;
        }
        int k = lo > NT ? NT : lo;           // first sorted idx with key > -sp
        size_t sidx = (size_t)(b*(NT+1) + k)*II + tid;
        float y = (sp * S1_scr[sidx] + S2_scr[sidx]) * inv_n;
        ypre_scr[(size_t)m*II + tid] = y;
    }
}

// ---------------- 9. out = BN(ypre @ ww + bw) + x  (M=16384,K=128,N=256) --------
__global__ __launch_bounds__(256) void final_gemm_kernel(
        const float* __restrict__ x, const float* __restrict__ ww,
        const float* __restrict__ bw, const float* __restrict__ gamma,
        const float* __restrict__ beta, const float* __restrict__ bn_mean,
        const float* __restrict__ bn_var, float* __restrict__ out) {
    __shared__ float as[16][128];
    __shared__ float bs[16][128];
    int m0 = blockIdx.x * 128;
    int n0 = blockIdx.y * 128;
    int tid = threadIdx.x;
    int tx = tid & 15, ty = tid >> 4;
    float acc[8][8] = {};
    for (int k0 = 0; k0 < II; k0 += 16) {
        #pragma unroll
        for (int i = 0; i < 2; i++) {
            int id = tid + i*256;
            int row = id >> 2, c4 = id & 3;
            float4 v = *(const float4*)(ypre_scr + (size_t)(m0+row)*II + k0 + c4*4);
            as[c4*4+0][row] = v.x; as[c4*4+1][row] = v.y;
            as[c4*4+2][row] = v.z; as[c4*4+3][row] = v.w;
        }
        #pragma unroll
        for (int i = 0; i < 2; i++) {
            int id = tid + i*256;
            int kr = id >> 5, c4 = id & 31;
            *(float4*)&bs[kr][c4*4] = *(const float4*)(ww + (size_t)(k0+kr)*CC + n0 + c4*4);
        }
        __syncthreads();
        #pragma unroll
        for (int kk = 0; kk < 16; kk++) {
            float ar[8], br[8];
            *(float4*)(ar)   = *(float4*)&as[kk][ty*8];
            *(float4*)(ar+4) = *(float4*)&as[kk][ty*8+4];
            *(float4*)(br)   = *(float4*)&bs[kk][tx*8];
            *(float4*)(br+4) = *(float4*)&bs[kk][tx*8+4];
            #pragma unroll
            for (int i = 0; i < 8; i++)
                #pragma unroll
                for (int j = 0; j < 8; j++)
                    acc[i][j] += ar[i] * br[j];
        }
        __syncthreads();
    }
    // fold BN into scale/shift per column: val = acc*sc + (bw*sc + beta - mean*sc) + x
    float scj[8], shj[8];
    #pragma unroll
    for (int j = 0; j < 8; j++) {
        int col = n0 + tx*8 + j;
        float sc = gamma[col] * rsqrtf(bn_var[col] + BN_EPS);
        scj[j] = sc;
        shj[j] = (bw[col] - bn_mean[col]) * sc + beta[col];
    }
    #pragma unroll
    for (int i = 0; i < 8; i++) {
        int row = m0 + ty*8 + i;
        const float* xr = x + (size_t)row*CC + n0 + tx*8;
        float4 x0 = *(const float4*)(xr);
        float4 x1 = *(const float4*)(xr + 4);
        float4 o0, o1;
        o0.x = acc[i][0]*scj[0] + shj[0] + x0.x;
        o0.y = acc[i][1]*scj[1] + shj[1] + x0.y;
        o0.z = acc[i][2]*scj[2] + shj[2] + x0.z;
        o0.w = acc[i][3]*scj[3] + shj[3] + x0.w;
        o1.x = acc[i][4]*scj[4] + shj[4] + x1.x;
        o1.y = acc[i][5]*scj[5] + shj[5] + x1.y;
        o1.z = acc[i][6]*scj[6] + shj[6] + x1.z;
        o1.w = acc[i][7]*scj[7] + shj[7] + x1.w;
        *(float4*)(out + (size_t)row*CC + n0 + tx*8)     = o0;
        *(float4*)(out + (size_t)row*CC + n0 + tx*8 + 4) = o1;
    }
}

// ---------------- launch ---------------------------------------------------------
extern "C" void kernel_launch(void* const* d_in, const int* in_sizes, int n_in,
                              void* d_out, int out_size) {
    const float* x     = (const float*)d_in[0];
    const float* wg    = (const float*)d_in[1];
    const float* bg    = (const float*)d_in[2];
    const float* wt    = (const float*)d_in[3];
    const float* bt    = (const float*)d_in[4];
    const float* wp    = (const float*)d_in[5];
    const float* bp    = (const float*)d_in[6];
    const float* wc    = (const float*)d_in[7];
    const float* ww    = (const float*)d_in[8];
    const float* bw    = (const float*)d_in[9];
    const float* gamma = (const float*)d_in[10];
    const float* beta  = (const float*)d_in[11];
    const float* bmean = (const float*)d_in[12];
    const float* bvar  = (const float*)d_in[13];
    float* out = (float*)d_out;

    prep_kernel<<<1, 256>>>(wt, bt, wp, bp, wc);
    scores_kernel<<<(BB*NT)/8, 256>>>(x);
    proj_gemm_kernel<<<(BB*NT)/128, 256>>>(x, wg, bg);
    sort_kernel<<<BB, 1024>>>();
    chunk_reduce_kernel<<<BB*NCH, 128>>>();
    chunk_suffix_kernel<<<BB, 128>>>();
    scan_fill_kernel<<<BB*NCH, 128>>>();
    ypre_kernel<<<dim3(NT/32, BB), 128>>>();
    final_gemm_kernel<<<dim3((BB*NT)/128, CC/128), 256>>>(
        x, ww, bw, gamma, beta, bmean, bvar, out);
}

// round 5
// speedup vs baseline: 1.4727x; 1.4727x over previous
#include <cuda_runtime.h>
#include <cstdint>

#define BB 4
#define NT 4096
#define CC 256
#define II 128
#define NCH 64          // chunks per batch for suffix scan
#define CH  64          // rows per chunk (NCH*CH == NT)
#define BN_EPS 1e-3f

// ---------------- scratch (static device allocations; no cudaMalloc) -----------
__device__ float g_scr[BB*NT*II];          // g_x = x@wg + bg
__device__ float st_scr[BB*NT];            // s_theta per row
__device__ float sp_scr[BB*NT];            // s_phi per row
__device__ float keys_scr[BB*NT];          // sorted s_theta
__device__ int   perm_scr[BB*NT];          // sort permutation
__device__ float S1_scr[BB*(NT+1)*II];     // suffix sums of g (sorted order)
__device__ float S2_scr[BB*(NT+1)*II];     // suffix sums of s_theta*g
__device__ float c1_scr[BB*NCH*II];        // per-chunk sums
__device__ float c2_scr[BB*NCH*II];
__device__ float e1_scr[BB*NCH*II];        // exclusive suffix of chunk sums
__device__ float e2_scr[BB*NCH*II];
__device__ float ypre_scr[BB*NT*II];       // y before trailing conv
__device__ float vproj_scr[2*CC+2];        // wt@wc1, wp@wc2, ct, cp

// ---------------- helpers -------------------------------------------------------
__device__ __forceinline__ uint32_t f2tf32(float f) {
    uint32_t u;
    asm("cvt.rna.tf32.f32 %0, %1;" : "=r"(u) : "f"(f));
    return u;
}

__device__ __forceinline__ void mma_tf32(float* d, const uint32_t* a,
                                         uint32_t b0, uint32_t b1) {
    asm volatile(
        "mma.sync.aligned.m16n8k8.row.col.f32.tf32.tf32.f32 "
        "{%0,%1,%2,%3}, {%4,%5,%6,%7}, {%8,%9}, {%0,%1,%2,%3};"
        : "+f"(d[0]), "+f"(d[1]), "+f"(d[2]), "+f"(d[3])
        : "r"(a[0]), "r"(a[1]), "r"(a[2]), "r"(a[3]), "r"(b0), "r"(b1));
}

__device__ __forceinline__ void cswap(float& a, float& b, int& ia, int& ib, bool up) {
    if ((a > b) == up) {
        float t = a; a = b; b = t;
        int ti = ia; ia = ib; ib = ti;
    }
}

// ---------------- 1. collapse score projections --------------------------------
__global__ __launch_bounds__(256) void prep_kernel(
        const float* __restrict__ wt, const float* __restrict__ bt,
        const float* __restrict__ wp, const float* __restrict__ bp,
        const float* __restrict__ wc) {
    int c = threadIdx.x;                    // 256 threads
    float vt = 0.f, vp = 0.f;
    #pragma unroll 4
    for (int k = 0; k < II; k++) {
        vt += wt[c*II + k] * wc[k];
        vp += wp[c*II + k] * wc[II + k];
    }
    vproj_scr[c]      = vt;
    vproj_scr[CC + c] = vp;
    if (c == 0) {
        float ct = 0.f, cp = 0.f;
        for (int k = 0; k < II; k++) { ct += bt[k]*wc[k]; cp += bp[k]*wc[II+k]; }
        vproj_scr[2*CC]   = ct;
        vproj_scr[2*CC+1] = cp;
    }
}

// ---------------- 2. per-row scalar scores --------------------------------------
__global__ __launch_bounds__(256) void scores_kernel(const float* __restrict__ x) {
    int warp = threadIdx.x >> 5, lane = threadIdx.x & 31;
    int m = blockIdx.x * 8 + warp;          // 8 warps/block, warp per row
    const float* xr = x + (size_t)m * CC;
    float at = 0.f, ap = 0.f;
    #pragma unroll
    for (int i = lane; i < CC; i += 32) {
        float xv = xr[i];
        at += xv * vproj_scr[i];
        ap += xv * vproj_scr[CC + i];
    }
    #pragma unroll
    for (int o = 16; o; o >>= 1) {
        at += __shfl_xor_sync(0xffffffffu, at, o);
        ap += __shfl_xor_sync(0xffffffffu, ap, o);
    }
    if (lane == 0) {
        st_scr[m] = at + vproj_scr[2*CC];
        sp_scr[m] = ap + vproj_scr[2*CC+1];
    }
}

// ---------------- 3. fused: tf32 proj GEMM (blocks 0..127) + sort (128..131) ----
// proj: g = x @ wg + bg,  M=16384, K=256, N=128
// smem layout (floats): A_s[128][36] at 0 (4608), B_s[32][136] at 4608 (4352)
// sort path reuses the same array: keys[4096] at 0, idx[4096] at 4096 (as int)
#define A_STRIDE 36
#define B_STRIDE 136
#define B_OFF    4608

__global__ __launch_bounds__(256) void proj_sort_kernel(
        const float* __restrict__ x, const float* __restrict__ wg,
        const float* __restrict__ bg) {
    __shared__ __align__(16) float smem_f[9216];   // 36 KB

    int tid = threadIdx.x;

    if (blockIdx.x < 128) {
        // ------------------- tf32 GEMM path -------------------
        uint32_t* As = (uint32_t*)smem_f;
        uint32_t* Bs = (uint32_t*)(smem_f + B_OFF);
        int m0 = blockIdx.x * 128;
        int wid = tid >> 5, lane = tid & 31;
        int wm = wid & 3, wn = wid >> 2;          // warp tile: 32m x 64n
        int lp4 = lane >> 2, lm4 = lane & 3;

        float acc[2][8][4];
        #pragma unroll
        for (int mi = 0; mi < 2; mi++)
            #pragma unroll
            for (int nt = 0; nt < 8; nt++)
                #pragma unroll
                for (int q = 0; q < 4; q++) acc[mi][nt][q] = 0.f;

        for (int kc = 0; kc < CC; kc += 32) {
            // stage A: 128 rows x 32 k (8 float4 per row)
            #pragma unroll
            for (int r = 0; r < 4; r++) {
                int idx = tid + r*256;            // 1024 float4 chunks
                int row = idx >> 3, c4 = idx & 7;
                float4 v = *(const float4*)(x + (size_t)(m0+row)*CC + kc + c4*4);
                uint4 t = make_uint4(f2tf32(v.x), f2tf32(v.y), f2tf32(v.z), f2tf32(v.w));
                *(uint4*)&As[row*A_STRIDE + c4*4] = t;
            }
            // stage B: 32 k-rows x 128 n (32 float4 per row)
            #pragma unroll
            for (int r = 0; r < 4; r++) {
                int idx = tid + r*256;
                int row = idx >> 5, c4 = idx & 31;
                float4 v = *(const float4*)(wg + (size_t)(kc+row)*II + c4*4);
                uint4 t = make_uint4(f2tf32(v.x), f2tf32(v.y), f2tf32(v.z), f2tf32(v.w));
                *(uint4*)&Bs[row*B_STRIDE + c4*4] = t;
            }
            __syncthreads();

            #pragma unroll
            for (int k8 = 0; k8 < 32; k8 += 8) {
                uint32_t afr[2][4];
                #pragma unroll
                for (int mi = 0; mi < 2; mi++) {
                    int rb = wm*32 + mi*16;
                    afr[mi][0] = As[(rb + lp4    )*A_STRIDE + k8 + lm4];
                    afr[mi][1] = As[(rb + lp4 + 8)*A_STRIDE + k8 + lm4];
                    afr[mi][2] = As[(rb + lp4    )*A_STRIDE + k8 + 4 + lm4];
                    afr[mi][3] = As[(rb + lp4 + 8)*A_STRIDE + k8 + 4 + lm4];
                }
                #pragma unroll
                for (int nt = 0; nt < 8; nt++) {
                    int nb = wn*64 + nt*8;
                    uint32_t b0 = Bs[(k8 + lm4    )*B_STRIDE + nb + lp4];
                    uint32_t b1 = Bs[(k8 + 4 + lm4)*B_STRIDE + nb + lp4];
                    mma_tf32(acc[0][nt], afr[0], b0, b1);
                    mma_tf32(acc[1][nt], afr[1], b0, b1);
                }
            }
            __syncthreads();
        }
        // epilogue: + bg, write g_scr
        #pragma unroll
        for (int mi = 0; mi < 2; mi++) {
            #pragma unroll
            for (int nt = 0; nt < 8; nt++) {
                int col = wn*64 + nt*8 + lm4*2;
                float bg0 = __ldg(bg + col), bg1 = __ldg(bg + col + 1);
                int r0 = m0 + wm*32 + mi*16 + lp4;
                float2 v0 = make_float2(acc[mi][nt][0] + bg0, acc[mi][nt][1] + bg1);
                float2 v1 = make_float2(acc[mi][nt][2] + bg0, acc[mi][nt][3] + bg1);
                *(float2*)&g_scr[(size_t)r0*II + col]       = v0;
                *(float2*)&g_scr[(size_t)(r0+8)*II + col]   = v1;
            }
        }
    } else {
        // ------------------- sort path (4 blocks, one per batch) -------------------
        float* k_sm = smem_f;
        int*   i_sm = (int*)(smem_f + NT);
        int b = blockIdx.x - 128;

        // stage 0: each thread sorts its 16 elements locally (k = 2..16)
        int base = tid * 16;
        float kk[16]; int ii[16];
        #pragma unroll
        for (int l = 0; l < 16; l++) { kk[l] = st_scr[b*NT + base + l]; ii[l] = base + l; }
        #pragma unroll
        for (int k2 = 2; k2 <= 16; k2 <<= 1) {
            #pragma unroll
            for (int j2 = k2 >> 1; j2 > 0; j2 >>= 1) {
                #pragma unroll
                for (int p = 0; p < 16; p++) {
                    if (!(p & j2)) {
                        bool up = (((base + p) & k2) == 0);
                        cswap(kk[p], kk[p + j2], ii[p], ii[p + j2], up);
                    }
                }
            }
        }
        #pragma unroll
        for (int l = 0; l < 16; l++) { k_sm[base + l] = kk[l]; i_sm[base + l] = ii[l]; }
        __syncthreads();

        // main merges
        for (int k = 32; k <= NT; k <<= 1) {
            for (int j = k >> 1; j >= 16; j >>= 1) {
                #pragma unroll
                for (int w = 0; w < 8; w++) {
                    int i = tid + w*256;                       // CE index 0..2047
                    int p = ((i & ~(j - 1)) << 1) | (i & (j - 1));
                    bool up = ((p & k) == 0);
                    float a = k_sm[p], c2 = k_sm[p + j];
                    if ((a > c2) == up) {
                        k_sm[p] = c2; k_sm[p + j] = a;
                        int t0 = i_sm[p]; i_sm[p] = i_sm[p + j]; i_sm[p + j] = t0;
                    }
                }
                __syncthreads();
            }
            // local merge of phases j = 8,4,2,1 (direction constant per 16-block)
            bool up = ((base & k) == 0);
            #pragma unroll
            for (int l = 0; l < 16; l++) { kk[l] = k_sm[base + l]; ii[l] = i_sm[base + l]; }
            #pragma unroll
            for (int j2 = 8; j2 > 0; j2 >>= 1) {
                #pragma unroll
                for (int p = 0; p < 16; p++) {
                    if (!(p & j2)) cswap(kk[p], kk[p + j2], ii[p], ii[p + j2], up);
                }
            }
            #pragma unroll
            for (int l = 0; l < 16; l++) { k_sm[base + l] = kk[l]; i_sm[base + l] = ii[l]; }
            __syncthreads();
        }

        #pragma unroll
        for (int w = 0; w < 16; w++) {
            int i = tid + w*256;
            keys_scr[b*NT + i] = k_sm[i];
            perm_scr[b*NT + i] = i_sm[i];
        }
    }
}

// ---------------- 5. chunk sums (reduction, high MLP) ---------------------------
__global__ __launch_bounds__(128) void chunk_reduce_kernel() {
    __shared__ int   perm_sm[CH];
    __shared__ float keys_sm[CH];
    int b = blockIdx.x / NCH, c = blockIdx.x % NCH;
    int tid = threadIdx.x;
    int base = b*NT + c*CH;
    if (tid < CH) { perm_sm[tid] = perm_scr[base + tid]; keys_sm[tid] = keys_scr[base + tid]; }
    __syncthreads();
    float a1 = 0.f, a2 = 0.f;
    #pragma unroll 8
    for (int j = 0; j < CH; j++) {
        float g = g_scr[(size_t)(b*NT + perm_sm[j])*II + tid];
        a1 += g;
        a2 += keys_sm[j] * g;
    }
    c1_scr[(size_t)blockIdx.x*II + tid] = a1;
    c2_scr[(size_t)blockIdx.x*II + tid] = a2;
}

// ---------------- 6. exclusive suffix over chunk sums ---------------------------
__global__ __launch_bounds__(128) void chunk_suffix_kernel() {
    int b = blockIdx.x, d = threadIdx.x;
    float a1 = 0.f, a2 = 0.f;
    for (int c = NCH - 1; c >= 0; c--) {
        size_t idx = (size_t)(b*NCH + c)*II + d;
        e1_scr[idx] = a1; e2_scr[idx] = a2;
        a1 += c1_scr[idx]; a2 += c2_scr[idx];
    }
    S1_scr[(size_t)(b*(NT+1) + NT)*II + d] = 0.f;
    S2_scr[(size_t)(b*(NT+1) + NT)*II + d] = 0.f;
}

// ---------------- 7. fill suffix-sum tables -------------------------------------
__global__ __launch_bounds__(128) void scan_fill_kernel() {
    __shared__ float g_sm[CH][II];   // 32 KB
    __shared__ int   perm_sm[CH];
    __shared__ float keys_sm[CH];
    int b = blockIdx.x / NCH, c = blockIdx.x % NCH;
    int tid = threadIdx.x;
    int base = b*NT + c*CH;
    if (tid < CH) { perm_sm[tid] = perm_scr[base + tid]; keys_sm[tid] = keys_scr[base + tid]; }
    __syncthreads();
    #pragma unroll 4
    for (int t = 0; t < CH; t++)
        g_sm[t][tid] = g_scr[(size_t)(b*NT + perm_sm[t])*II + tid];
    __syncthreads();
    float a1 = e1_scr[(size_t)(b*NCH + c)*II + tid];
    float a2 = e2_scr[(size_t)(b*NCH + c)*II + tid];
    for (int j = CH - 1; j >= 0; j--) {
        float g = g_sm[j][tid];
        a1 += g;
        a2 += keys_sm[j] * g;
        int pos = c*CH + j;
        S1_scr[(size_t)(b*(NT+1) + pos)*II + tid] = a1;
        S2_scr[(size_t)(b*(NT+1) + pos)*II + tid] = a2;
    }
}

// ---------------- 8. y_pre via binary search + rank-1 combine -------------------
__global__ __launch_bounds__(128) void ypre_kernel() {
    __shared__ float keys_sm[NT];    // 16 KB
    int b = blockIdx.y, tid = threadIdx.x;
    for (int i = tid; i < NT; i += 128) keys_sm[i] = keys_scr[b*NT + i];
    __syncthreads();
    const float inv_n = 1.0f / (float)NT;
    for (int r = 0; r < 32; r++) {
        int row = blockIdx.x * 32 + r;
        int m = b*NT + row;
        float sp = sp_scr[m];
        float t = -sp;
        int lo = 0, hi = NT;
        #pragma unroll
        for (int it = 0; it < 12; it++) {   // covers range [0,4096]
            int mid = (lo + hi) >> 1;
            float kv = (mid < NT) ? keys_sm[mid] : __int_as_float(0x7f800000);
            if (kv > t) hi = mid; else lo = mid + 1;
        }
        int k = lo > NT ? NT : lo;           // first sorted idx with key > -sp
        size_t sidx = (size_t)(b*(NT+1) + k)*II + tid;
        float y = (sp * S1_scr[sidx] + S2_scr[sidx]) * inv_n;
        ypre_scr[(size_t)m*II + tid] = y;
    }
}

// ---------------- 9. tf32 final GEMM: out = BN(ypre @ ww + bw) + x --------------
// M=16384, K=128, N=256; block tile 128m x 128n, grid (128, 2)
__global__ __launch_bounds__(256) void final_gemm_kernel(
        const float* __restrict__ x, const float* __restrict__ ww,
        const float* __restrict__ bw, const float* __restrict__ gamma,
        const float* __restrict__ beta, const float* __restrict__ bn_mean,
        const float* __restrict__ bn_var, float* __restrict__ out) {
    __shared__ __align__(16) float smem_f[9216];
    uint32_t* As = (uint32_t*)smem_f;
    uint32_t* Bs = (uint32_t*)(smem_f + B_OFF);
    float* sc_sm = smem_f + 8960;   // 128
    float* sh_sm = smem_f + 9088;   // 128

    int tid = threadIdx.x;
    int m0 = blockIdx.x * 128;
    int n0 = blockIdx.y * 128;
    int wid = tid >> 5, lane = tid & 31;
    int wm = wid & 3, wn = wid >> 2;
    int lp4 = lane >> 2, lm4 = lane & 3;

    if (tid < 128) {
        int col = n0 + tid;
        float sc = gamma[col] * rsqrtf(bn_var[col] + BN_EPS);
        sc_sm[tid] = sc;
        sh_sm[tid] = (bw[col] - bn_mean[col]) * sc + beta[col];
    }

    float acc[2][8][4];
    #pragma unroll
    for (int mi = 0; mi < 2; mi++)
        #pragma unroll
        for (int nt = 0; nt < 8; nt++)
            #pragma unroll
            for (int q = 0; q < 4; q++) acc[mi][nt][q] = 0.f;

    for (int kc = 0; kc < II; kc += 32) {
        // stage A: 128 rows x 32 k (8 float4 per row)
        #pragma unroll
        for (int r = 0; r < 4; r++) {
            int idx = tid + r*256;
            int row = idx >> 3, c4 = idx & 7;
            float4 v = *(const float4*)(ypre_scr + (size_t)(m0+row)*II + kc + c4*4);
            uint4 t = make_uint4(f2tf32(v.x), f2tf32(v.y), f2tf32(v.z), f2tf32(v.w));
            *(uint4*)&As[row*A_STRIDE + c4*4] = t;
        }
        // stage B: 32 k-rows x 128 n (32 float4 per row)
        #pragma unroll
        for (int r = 0; r < 4; r++) {
            int idx = tid + r*256;
            int row = idx >> 5, c4 = idx & 31;
            float4 v = *(const float4*)(ww + (size_t)(kc+row)*CC + n0 + c4*4);
            uint4 t = make_uint4(f2tf32(v.x), f2tf32(v.y), f2tf32(v.z), f2tf32(v.w));
            *(uint4*)&Bs[row*B_STRIDE + c4*4] = t;
        }
        __syncthreads();

        #pragma unroll
        for (int k8 = 0; k8 < 32; k8 += 8) {
            uint32_t afr[2][4];
            #pragma unroll
            for (int mi = 0; mi < 2; mi++) {
                int rb = wm*32 + mi*16;
                afr[mi][0] = As[(rb + lp4    )*A_STRIDE + k8 + lm4];
                afr[mi][1] = As[(rb + lp4 + 8)*A_STRIDE + k8 + lm4];
                afr[mi][2] = As[(rb + lp4    )*A_STRIDE + k8 + 4 + lm4];
                afr[mi][3] = As[(rb + lp4 + 8)*A_STRIDE + k8 + 4 + lm4];
            }
            #pragma unroll
            for (int nt = 0; nt < 8; nt++) {
                int nb = wn*64 + nt*8;
                uint32_t b0 = Bs[(k8 + lm4    )*B_STRIDE + nb + lp4];
                uint32_t b1 = Bs[(k8 + 4 + lm4)*B_STRIDE + nb + lp4];
                mma_tf32(acc[0][nt], afr[0], b0, b1);
                mma_tf32(acc[1][nt], afr[1], b0, b1);
            }
        }
        __syncthreads();
    }

    #pragma unroll
    for (int mi = 0; mi < 2; mi++) {
        #pragma unroll
        for (int nt = 0; nt < 8; nt++) {
            int lc = wn*64 + nt*8 + lm4*2;    // 0..127 within tile
            float s0 = sc_sm[lc], s1 = sc_sm[lc+1];
            float h0 = sh_sm[lc], h1 = sh_sm[lc+1];
            int r0 = m0 + wm*32 + mi*16 + lp4;
            const float* xr0 = x + (size_t)r0*CC + n0 + lc;
            const float* xr1 = x + (size_t)(r0+8)*CC + n0 + lc;
            float2 x0 = *(const float2*)xr0;
            float2 x1 = *(const float2*)xr1;
            float2 v0 = make_float2(acc[mi][nt][0]*s0 + h0 + x0.x,
                                    acc[mi][nt][1]*s1 + h1 + x0.y);
            float2 v1 = make_float2(acc[mi][nt][2]*s0 + h0 + x1.x,
                                    acc[mi][nt][3]*s1 + h1 + x1.y);
            *(float2*)(out + (size_t)r0*CC + n0 + lc)     = v0;
            *(float2*)(out + (size_t)(r0+8)*CC + n0 + lc) = v1;
        }
    }
}

// ---------------- launch ---------------------------------------------------------
extern "C" void kernel_launch(void* const* d_in, const int* in_sizes, int n_in,
                              void* d_out, int out_size) {
    const float* x     = (const float*)d_in[0];
    const float* wg    = (const float*)d_in[1];
    const float* bg    = (const float*)d_in[2];
    const float* wt    = (const float*)d_in[3];
    const float* bt    = (const float*)d_in[4];
    const float* wp    = (const float*)d_in[5];
    const float* bp    = (const float*)d_in[6];
    const float* wc    = (const float*)d_in[7];
    const float* ww    = (const float*)d_in[8];
    const float* bw    = (const float*)d_in[9];
    const float* gamma = (const float*)d_in[10];
    const float* beta  = (const float*)d_in[11];
    const float* bmean = (const float*)d_in[12];
    const float* bvar  = (const float*)d_in[13];
    float* out = (float*)d_out;

    prep_kernel<<<1, 256>>>(wt, bt, wp, bp, wc);
    scores_kernel<<<(BB*NT)/8, 256>>>(x);
    proj_sort_kernel<<<128 + BB, 256>>>(x, wg, bg);   // GEMM blocks + sort blocks
    chunk_reduce_kernel<<<BB*NCH, 128>>>();
    chunk_suffix_kernel<<<BB, 128>>>();
    scan_fill_kernel<<<BB*NCH, 128>>>();
    ypre_kernel<<<dim3(NT/32, BB), 128>>>();
    final_gemm_kernel<<<dim3((BB*NT)/128, CC/128), 256>>>(
        x, ww, bw, gamma, beta, bmean, bvar, out);
}

// round 6
// speedup vs baseline: 1.5107x; 1.0258x over previous
#include <cuda_runtime.h>
#include <cstdint>

#define BB 4
#define NT 4096
#define CC 256
#define II 128
#define NCH 128         // chunks per batch for suffix scan
#define CH  32          // rows per chunk (NCH*CH == NT)
#define BN_EPS 1e-3f

// ---------------- scratch (static device allocations; no cudaMalloc) -----------
__device__ float  g_scr[BB*NT*II];           // g_x = x@wg + bg
__device__ float  st_scr[BB*NT];             // s_theta per row
__device__ float  sp_scr[BB*NT];             // s_phi per row
__device__ float  keys_scr[BB*NT];           // sorted s_theta
__device__ int    perm_scr[BB*NT];           // sort permutation
__device__ float2 S12_scr[BB*(NT+1)*II];     // interleaved suffix sums {S1,S2}
__device__ float2 c12_scr[BB*NCH*II];        // per-chunk sums {c1,c2}
__device__ float2 e12_scr[BB*NCH*II];        // exclusive suffix of chunk sums
__device__ float  vproj_scr[2*CC+2];         // wt@wc1, wp@wc2, ct, cp

// ---------------- helpers -------------------------------------------------------
__device__ __forceinline__ uint32_t f2tf32(float f) {
    uint32_t u;
    asm("cvt.rna.tf32.f32 %0, %1;" : "=r"(u) : "f"(f));
    return u;
}

__device__ __forceinline__ void mma_tf32(float* d, const uint32_t* a,
                                         uint32_t b0, uint32_t b1) {
    asm volatile(
        "mma.sync.aligned.m16n8k8.row.col.f32.tf32.tf32.f32 "
        "{%0,%1,%2,%3}, {%4,%5,%6,%7}, {%8,%9}, {%0,%1,%2,%3};"
        : "+f"(d[0]), "+f"(d[1]), "+f"(d[2]), "+f"(d[3])
        : "r"(a[0]), "r"(a[1]), "r"(a[2]), "r"(a[3]), "r"(b0), "r"(b1));
}

__device__ __forceinline__ void cswap(float& a, float& b, int& ia, int& ib, bool up) {
    if ((a > b) == up) {
        float t = a; a = b; b = t;
        int ti = ia; ia = ib; ib = ti;
    }
}

// ---------------- 1. collapse score projections --------------------------------
__global__ __launch_bounds__(256) void prep_kernel(
        const float* __restrict__ wt, const float* __restrict__ bt,
        const float* __restrict__ wp, const float* __restrict__ bp,
        const float* __restrict__ wc) {
    int c = threadIdx.x;                    // 256 threads
    float vt = 0.f, vp = 0.f;
    #pragma unroll 4
    for (int k = 0; k < II; k++) {
        vt += wt[c*II + k] * wc[k];
        vp += wp[c*II + k] * wc[II + k];
    }
    vproj_scr[c]      = vt;
    vproj_scr[CC + c] = vp;
    if (c == 0) {
        float ct = 0.f, cp = 0.f;
        for (int k = 0; k < II; k++) { ct += bt[k]*wc[k]; cp += bp[k]*wc[II+k]; }
        vproj_scr[2*CC]   = ct;
        vproj_scr[2*CC+1] = cp;
    }
}

// ---------------- 2. per-row scalar scores --------------------------------------
__global__ __launch_bounds__(256) void scores_kernel(const float* __restrict__ x) {
    int warp = threadIdx.x >> 5, lane = threadIdx.x & 31;
    int m = blockIdx.x * 8 + warp;          // 8 warps/block, warp per row
    const float* xr = x + (size_t)m * CC;
    float at = 0.f, ap = 0.f;
    #pragma unroll
    for (int i = lane; i < CC; i += 32) {
        float xv = xr[i];
        at += xv * vproj_scr[i];
        ap += xv * vproj_scr[CC + i];
    }
    #pragma unroll
    for (int o = 16; o; o >>= 1) {
        at += __shfl_xor_sync(0xffffffffu, at, o);
        ap += __shfl_xor_sync(0xffffffffu, ap, o);
    }
    if (lane == 0) {
        st_scr[m] = at + vproj_scr[2*CC];
        sp_scr[m] = ap + vproj_scr[2*CC+1];
    }
}

// ---------------- 3. fused: tf32 proj GEMM (blocks 0..127) + sort (128..131) ----
#define A_STRIDE 36
#define B_STRIDE 136
#define B_OFF    4608

__global__ __launch_bounds__(256) void proj_sort_kernel(
        const float* __restrict__ x, const float* __restrict__ wg,
        const float* __restrict__ bg) {
    __shared__ __align__(16) float smem_f[9216];   // 36 KB

    int tid = threadIdx.x;

    if (blockIdx.x < 128) {
        // ------------------- tf32 GEMM path -------------------
        uint32_t* As = (uint32_t*)smem_f;
        uint32_t* Bs = (uint32_t*)(smem_f + B_OFF);
        int m0 = blockIdx.x * 128;
        int wid = tid >> 5, lane = tid & 31;
        int wm = wid & 3, wn = wid >> 2;          // warp tile: 32m x 64n
        int lp4 = lane >> 2, lm4 = lane & 3;

        float acc[2][8][4];
        #pragma unroll
        for (int mi = 0; mi < 2; mi++)
            #pragma unroll
            for (int nt = 0; nt < 8; nt++)
                #pragma unroll
                for (int q = 0; q < 4; q++) acc[mi][nt][q] = 0.f;

        for (int kc = 0; kc < CC; kc += 32) {
            #pragma unroll
            for (int r = 0; r < 4; r++) {       // A: 128 rows x 32 k
                int idx = tid + r*256;
                int row = idx >> 3, c4 = idx & 7;
                float4 v = *(const float4*)(x + (size_t)(m0+row)*CC + kc + c4*4);
                uint4 t = make_uint4(f2tf32(v.x), f2tf32(v.y), f2tf32(v.z), f2tf32(v.w));
                *(uint4*)&As[row*A_STRIDE + c4*4] = t;
            }
            #pragma unroll
            for (int r = 0; r < 4; r++) {       // B: 32 k-rows x 128 n
                int idx = tid + r*256;
                int row = idx >> 5, c4 = idx & 31;
                float4 v = *(const float4*)(wg + (size_t)(kc+row)*II + c4*4);
                uint4 t = make_uint4(f2tf32(v.x), f2tf32(v.y), f2tf32(v.z), f2tf32(v.w));
                *(uint4*)&Bs[row*B_STRIDE + c4*4] = t;
            }
            __syncthreads();

            #pragma unroll
            for (int k8 = 0; k8 < 32; k8 += 8) {
                uint32_t afr[2][4];
                #pragma unroll
                for (int mi = 0; mi < 2; mi++) {
                    int rb = wm*32 + mi*16;
                    afr[mi][0] = As[(rb + lp4    )*A_STRIDE + k8 + lm4];
                    afr[mi][1] = As[(rb + lp4 + 8)*A_STRIDE + k8 + lm4];
                    afr[mi][2] = As[(rb + lp4    )*A_STRIDE + k8 + 4 + lm4];
                    afr[mi][3] = As[(rb + lp4 + 8)*A_STRIDE + k8 + 4 + lm4];
                }
                #pragma unroll
                for (int nt = 0; nt < 8; nt++) {
                    int nb = wn*64 + nt*8;
                    uint32_t b0 = Bs[(k8 + lm4    )*B_STRIDE + nb + lp4];
                    uint32_t b1 = Bs[(k8 + 4 + lm4)*B_STRIDE + nb + lp4];
                    mma_tf32(acc[0][nt], afr[0], b0, b1);
                    mma_tf32(acc[1][nt], afr[1], b0, b1);
                }
            }
            __syncthreads();
        }
        #pragma unroll
        for (int mi = 0; mi < 2; mi++) {
            #pragma unroll
            for (int nt = 0; nt < 8; nt++) {
                int col = wn*64 + nt*8 + lm4*2;
                float bg0 = __ldg(bg + col), bg1 = __ldg(bg + col + 1);
                int r0 = m0 + wm*32 + mi*16 + lp4;
                float2 v0 = make_float2(acc[mi][nt][0] + bg0, acc[mi][nt][1] + bg1);
                float2 v1 = make_float2(acc[mi][nt][2] + bg0, acc[mi][nt][3] + bg1);
                *(float2*)&g_scr[(size_t)r0*II + col]       = v0;
                *(float2*)&g_scr[(size_t)(r0+8)*II + col]   = v1;
            }
        }
    } else {
        // ------------------- sort path (4 blocks, one per batch) -------------------
        float* k_sm = smem_f;
        int*   i_sm = (int*)(smem_f + NT);
        int b = blockIdx.x - 128;

        int base = tid * 16;
        float kk[16]; int ii[16];
        #pragma unroll
        for (int l = 0; l < 16; l++) { kk[l] = st_scr[b*NT + base + l]; ii[l] = base + l; }
        #pragma unroll
        for (int k2 = 2; k2 <= 16; k2 <<= 1) {
            #pragma unroll
            for (int j2 = k2 >> 1; j2 > 0; j2 >>= 1) {
                #pragma unroll
                for (int p = 0; p < 16; p++) {
                    if (!(p & j2)) {
                        bool up = (((base + p) & k2) == 0);
                        cswap(kk[p], kk[p + j2], ii[p], ii[p + j2], up);
                    }
                }
            }
        }
        #pragma unroll
        for (int l = 0; l < 16; l++) { k_sm[base + l] = kk[l]; i_sm[base + l] = ii[l]; }
        __syncthreads();

        for (int k = 32; k <= NT; k <<= 1) {
            for (int j = k >> 1; j >= 16; j >>= 1) {
                #pragma unroll
                for (int w = 0; w < 8; w++) {
                    int i = tid + w*256;
                    int p = ((i & ~(j - 1)) << 1) | (i & (j - 1));
                    bool up = ((p & k) == 0);
                    float a = k_sm[p], c2 = k_sm[p + j];
                    if ((a > c2) == up) {
                        k_sm[p] = c2; k_sm[p + j] = a;
                        int t0 = i_sm[p]; i_sm[p] = i_sm[p + j]; i_sm[p + j] = t0;
                    }
                }
                __syncthreads();
            }
            bool up = ((base & k) == 0);
            #pragma unroll
            for (int l = 0; l < 16; l++) { kk[l] = k_sm[base + l]; ii[l] = i_sm[base + l]; }
            #pragma unroll
            for (int j2 = 8; j2 > 0; j2 >>= 1) {
                #pragma unroll
                for (int p = 0; p < 16; p++) {
                    if (!(p & j2)) cswap(kk[p], kk[p + j2], ii[p], ii[p + j2], up);
                }
            }
            #pragma unroll
            for (int l = 0; l < 16; l++) { k_sm[base + l] = kk[l]; i_sm[base + l] = ii[l]; }
            __syncthreads();
        }

        #pragma unroll
        for (int w = 0; w < 16; w++) {
            int i = tid + w*256;
            keys_scr[b*NT + i] = k_sm[i];
            perm_scr[b*NT + i] = i_sm[i];
        }
    }
}

// ---------------- 4. chunk sums (512 blocks, CH=32) -----------------------------
__global__ __launch_bounds__(128) void chunk_reduce_kernel() {
    __shared__ int   perm_sm[CH];
    __shared__ float keys_sm[CH];
    int b = blockIdx.x >> 7, c = blockIdx.x & (NCH-1);
    int tid = threadIdx.x;
    int base = b*NT + c*CH;
    if (tid < CH) { perm_sm[tid] = perm_scr[base + tid]; keys_sm[tid] = keys_scr[base + tid]; }
    __syncthreads();
    float a1 = 0.f, a2 = 0.f;
    #pragma unroll 8
    for (int j = 0; j < CH; j++) {
        float g = g_scr[(size_t)(b*NT + perm_sm[j])*II + tid];
        a1 += g;
        a2 += keys_sm[j] * g;
    }
    c12_scr[(size_t)blockIdx.x*II + tid] = make_float2(a1, a2);
}

// ---------------- 5. exclusive suffix over chunk sums + sentinel ----------------
__global__ __launch_bounds__(128) void chunk_suffix_kernel() {
    int b = blockIdx.x, d = threadIdx.x;
    float a1 = 0.f, a2 = 0.f;
    for (int c = NCH - 1; c >= 0; c--) {
        size_t idx = (size_t)(b*NCH + c)*II + d;
        e12_scr[idx] = make_float2(a1, a2);
        float2 v = c12_scr[idx];
        a1 += v.x; a2 += v.y;
    }
    S12_scr[(size_t)(b*(NT+1) + NT)*II + d] = make_float2(0.f, 0.f);
}

// ---------------- 6. fill interleaved suffix-sum table --------------------------
__global__ __launch_bounds__(128) void scan_fill_kernel() {
    __shared__ float g_sm[CH][II];   // 16 KB
    __shared__ int   perm_sm[CH];
    __shared__ float keys_sm[CH];
    int b = blockIdx.x >> 7, c = blockIdx.x & (NCH-1);
    int tid = threadIdx.x;
    int base = b*NT + c*CH;
    if (tid < CH) { perm_sm[tid] = perm_scr[base + tid]; keys_sm[tid] = keys_scr[base + tid]; }
    __syncthreads();
    #pragma unroll 4
    for (int t = 0; t < CH; t++)
        g_sm[t][tid] = g_scr[(size_t)(b*NT + perm_sm[t])*II + tid];
    __syncthreads();
    float2 e = e12_scr[(size_t)(b*NCH + c)*II + tid];
    float a1 = e.x, a2 = e.y;
    for (int j = CH - 1; j >= 0; j--) {
        float g = g_sm[j][tid];
        a1 += g;
        a2 += keys_sm[j] * g;
        int pos = c*CH + j;
        S12_scr[(size_t)(b*(NT+1) + pos)*II + tid] = make_float2(a1, a2);
    }
}

// ---------------- 7. fused final: ypre (search+gather) + tf32 GEMM + BN + res ---
// Block: 128m x 256n (full N), K=128, grid=128, 256 threads, dynamic smem.
// smem floats: keys[4096] | kidx(int)[128] | sp[128] | sc[256] | sh[256]
//              | A tf32 [128][132] | B tf32 [32][264]
#define F_KEYS 0
#define F_KIDX 4096
#define F_SP   4224
#define F_SC   4352
#define F_SH   4608
#define F_A    4864
#define FA_STRIDE 132
#define F_B    (F_A + 128*FA_STRIDE)          // 4864 + 16896 = 21760
#define FB_STRIDE 264
#define F_TOTAL (F_B + 32*FB_STRIDE)          // 21760 + 8448 = 30208 floats
#define F_SMEM_BYTES (F_TOTAL * 4)            // 120832 bytes

__global__ __launch_bounds__(256) void final_mega_kernel(
        const float* __restrict__ x, const float* __restrict__ ww,
        const float* __restrict__ bw, const float* __restrict__ gamma,
        const float* __restrict__ beta, const float* __restrict__ bn_mean,
        const float* __restrict__ bn_var, float* __restrict__ out) {
    extern __shared__ __align__(16) float smem[];
    float*    keys_sm = smem + F_KEYS;
    int*      kidx_sm = (int*)(smem + F_KIDX);
    float*    sp_sm   = smem + F_SP;
    float*    sc_sm   = smem + F_SC;
    float*    sh_sm   = smem + F_SH;
    uint32_t* As      = (uint32_t*)(smem + F_A);
    uint32_t* Bs      = (uint32_t*)(smem + F_B);

    int tid = threadIdx.x;
    int m0  = blockIdx.x * 128;
    int b   = m0 >> 12;                        // batch = m0 / 4096

    // ---- phase 0: load keys, sp, fold BN constants ----
    for (int i = tid; i < NT; i += 256) keys_sm[i] = keys_scr[b*NT + i];
    if (tid < 128) sp_sm[tid] = sp_scr[m0 + tid];
    {
        float sc = gamma[tid] * rsqrtf(bn_var[tid] + BN_EPS);
        sc_sm[tid] = sc;
        sh_sm[tid] = (bw[tid] - bn_mean[tid]) * sc + beta[tid];
    }
    __syncthreads();

    // ---- phase 1a: parallel binary searches (one thread per row) ----
    if (tid < 128) {
        float t = -sp_sm[tid];
        int lo = 0, hi = NT;
        #pragma unroll
        for (int it = 0; it < 12; it++) {
            int mid = (lo + hi) >> 1;
            float kv = (mid < NT) ? keys_sm[mid] : __int_as_float(0x7f800000);
            if (kv > t) hi = mid; else lo = mid + 1;
        }
        kidx_sm[tid] = lo > NT ? NT : lo;
    }
    __syncthreads();

    // ---- phase 1b: gather S12 rows, build A = ypre (tf32) in smem ----
    {
        int h = tid >> 7, l = tid & 127;       // two 128-thread groups, 64 rows each
        const float inv_n = 1.0f / (float)NT;
        #pragma unroll 4
        for (int r = h*64; r < h*64 + 64; r++) {
            int k = kidx_sm[r];
            float2 s = S12_scr[(size_t)(b*(NT+1) + k)*II + l];
            float y = (sp_sm[r]*s.x + s.y) * inv_n;
            As[r*FA_STRIDE + l] = f2tf32(y);
        }
    }
    __syncthreads();

    // ---- phase 2: tf32 GEMM 128x256x128 ----
    int wid = tid >> 5, lane = tid & 31;
    int wm = wid & 3, wn = wid >> 2;           // warp tile: 32m x 128n
    int lp4 = lane >> 2, lm4 = lane & 3;

    float acc[2][16][4];
    #pragma unroll
    for (int mi = 0; mi < 2; mi++)
        #pragma unroll
        for (int nt = 0; nt < 16; nt++)
            #pragma unroll
            for (int q = 0; q < 4; q++) acc[mi][nt][q] = 0.f;

    for (int kc = 0; kc < II; kc += 32) {
        // stage B: 32 k-rows x 256 n (64 float4 per row)
        #pragma unroll
        for (int r = 0; r < 8; r++) {
            int idx = tid + r*256;
            int row = idx >> 6, c4 = idx & 63;
            float4 v = *(const float4*)(ww + (size_t)(kc+row)*CC + c4*4);
            uint4 t = make_uint4(f2tf32(v.x), f2tf32(v.y), f2tf32(v.z), f2tf32(v.w));
            *(uint4*)&Bs[row*FB_STRIDE + c4*4] = t;
        }
        __syncthreads();

        #pragma unroll
        for (int k8 = 0; k8 < 32; k8 += 8) {
            int kA = kc + k8;
            uint32_t afr[2][4];
            #pragma unroll
            for (int mi = 0; mi < 2; mi++) {
                int rb = wm*32 + mi*16;
                afr[mi][0] = As[(rb + lp4    )*FA_STRIDE + kA + lm4];
                afr[mi][1] = As[(rb + lp4 + 8)*FA_STRIDE + kA + lm4];
                afr[mi][2] = As[(rb + lp4    )*FA_STRIDE + kA + 4 + lm4];
                afr[mi][3] = As[(rb + lp4 + 8)*FA_STRIDE + kA + 4 + lm4];
            }
            #pragma unroll
            for (int nt = 0; nt < 16; nt++) {
                int nb = wn*128 + nt*8;
                uint32_t b0 = Bs[(k8 + lm4    )*FB_STRIDE + nb + lp4];
                uint32_t b1 = Bs[(k8 + 4 + lm4)*FB_STRIDE + nb + lp4];
                mma_tf32(acc[0][nt], afr[0], b0, b1);
                mma_tf32(acc[1][nt], afr[1], b0, b1);
            }
        }
        __syncthreads();
    }

    // ---- epilogue: BN scale/shift + residual ----
    #pragma unroll
    for (int mi = 0; mi < 2; mi++) {
        #pragma unroll
        for (int nt = 0; nt < 16; nt++) {
            int col = wn*128 + nt*8 + lm4*2;
            float s0 = sc_sm[col], s1 = sc_sm[col+1];
            float h0 = sh_sm[col], h1 = sh_sm[col+1];
            int r0 = m0 + wm*32 + mi*16 + lp4;
            float2 x0 = *(const float2*)(x + (size_t)r0*CC + col);
            float2 x1 = *(const float2*)(x + (size_t)(r0+8)*CC + col);
            float2 v0 = make_float2(acc[mi][nt][0]*s0 + h0 + x0.x,
                                    acc[mi][nt][1]*s1 + h1 + x0.y);
            float2 v1 = make_float2(acc[mi][nt][2]*s0 + h0 + x1.x,
                                    acc[mi][nt][3]*s1 + h1 + x1.y);
            *(float2*)(out + (size_t)r0*CC + col)     = v0;
            *(float2*)(out + (size_t)(r0+8)*CC + col) = v1;
        }
    }
}

// ---------------- launch ---------------------------------------------------------
extern "C" void kernel_launch(void* const* d_in, const int* in_sizes, int n_in,
                              void* d_out, int out_size) {
    const float* x     = (const float*)d_in[0];
    const float* wg    = (const float*)d_in[1];
    const float* bg    = (const float*)d_in[2];
    const float* wt    = (const float*)d_in[3];
    const float* bt    = (const float*)d_in[4];
    const float* wp    = (const float*)d_in[5];
    const float* bp    = (const float*)d_in[6];
    const float* wc    = (const float*)d_in[7];
    const float* ww    = (const float*)d_in[8];
    const float* bw    = (const float*)d_in[9];
    const float* gamma = (const float*)d_in[10];
    const float* beta  = (const float*)d_in[11];
    const float* bmean = (const float*)d_in[12];
    const float* bvar  = (const float*)d_in[13];
    float* out = (float*)d_out;

    static bool attr_set = false;
    if (!attr_set) {
        cudaFuncSetAttribute(final_mega_kernel,
                             cudaFuncAttributeMaxDynamicSharedMemorySize,
                             F_SMEM_BYTES);
        attr_set = true;
    }

    prep_kernel<<<1, 256>>>(wt, bt, wp, bp, wc);
    scores_kernel<<<(BB*NT)/8, 256>>>(x);
    proj_sort_kernel<<<128 + BB, 256>>>(x, wg, bg);
    chunk_reduce_kernel<<<BB*NCH, 128>>>();
    chunk_suffix_kernel<<<BB, 128>>>();
    scan_fill_kernel<<<BB*NCH, 128>>>();
    final_mega_kernel<<<128, 256, F_SMEM_BYTES>>>(
        x, ww, bw, gamma, beta, bmean, bvar, out);
}

// round 7
// speedup vs baseline: 1.5305x; 1.0132x over previous
#include <cuda_runtime.h>
#include <cstdint>

#define BB 4
#define NT 4096
#define CC 256
#define II 128
#define NCH 128         // chunks per batch for suffix scan
#define CH  32          // rows per chunk (NCH*CH == NT)
#define BN_EPS 1e-3f

// ---------------- scratch (static device allocations; no cudaMalloc) -----------
__device__ float  g_scr[BB*NT*II];           // g_x = x@wg + bg
__device__ float  st_scr[BB*NT];             // s_theta per row
__device__ float  sp_scr[BB*NT];             // s_phi per row
__device__ float  keys_scr[BB*NT];           // sorted s_theta
__device__ int    perm_scr[BB*NT];           // sort permutation
__device__ float2 S12_scr[BB*(NT+1)*II];     // interleaved suffix sums {S1,S2}
__device__ float2 c12_scr[BB*NCH*II];        // per-chunk sums {c1,c2}
__device__ float2 e12_scr[BB*NCH*II];        // exclusive suffix of chunk sums
__device__ float  vproj_scr[2*CC+2];         // wt@wc1, wp@wc2, ct, cp

// ---------------- helpers -------------------------------------------------------
__device__ __forceinline__ uint32_t f2tf32(float f) {
    uint32_t u;
    asm("cvt.rna.tf32.f32 %0, %1;" : "=r"(u) : "f"(f));
    return u;
}

__device__ __forceinline__ void mma_tf32(float* d, const uint32_t* a,
                                         uint32_t b0, uint32_t b1) {
    asm volatile(
        "mma.sync.aligned.m16n8k8.row.col.f32.tf32.tf32.f32 "
        "{%0,%1,%2,%3}, {%4,%5,%6,%7}, {%8,%9}, {%0,%1,%2,%3};"
        : "+f"(d[0]), "+f"(d[1]), "+f"(d[2]), "+f"(d[3])
        : "r"(a[0]), "r"(a[1]), "r"(a[2]), "r"(a[3]), "r"(b0), "r"(b1));
}

__device__ __forceinline__ void cswap(float& a, float& b, int& ia, int& ib, bool up) {
    if ((a > b) == up) {
        float t = a; a = b; b = t;
        int ti = ia; ia = ib; ib = ti;
    }
}

// ---------------- 1. collapse score projections --------------------------------
__global__ __launch_bounds__(256) void prep_kernel(
        const float* __restrict__ wt, const float* __restrict__ bt,
        const float* __restrict__ wp, const float* __restrict__ bp,
        const float* __restrict__ wc) {
    int c = threadIdx.x;                    // 256 threads
    float vt = 0.f, vp = 0.f;
    #pragma unroll 4
    for (int k = 0; k < II; k++) {
        vt += wt[c*II + k] * wc[k];
        vp += wp[c*II + k] * wc[II + k];
    }
    vproj_scr[c]      = vt;
    vproj_scr[CC + c] = vp;
    if (c == 0) {
        float ct = 0.f, cp = 0.f;
        for (int k = 0; k < II; k++) { ct += bt[k]*wc[k]; cp += bp[k]*wc[II+k]; }
        vproj_scr[2*CC]   = ct;
        vproj_scr[2*CC+1] = cp;
    }
}

// ---------------- 2. per-row scalar scores --------------------------------------
__global__ __launch_bounds__(256) void scores_kernel(const float* __restrict__ x) {
    int warp = threadIdx.x >> 5, lane = threadIdx.x & 31;
    int m = blockIdx.x * 8 + warp;          // 8 warps/block, warp per row
    const float* xr = x + (size_t)m * CC;
    float at = 0.f, ap = 0.f;
    #pragma unroll
    for (int i = lane; i < CC; i += 32) {
        float xv = xr[i];
        at += xv * vproj_scr[i];
        ap += xv * vproj_scr[CC + i];
    }
    #pragma unroll
    for (int o = 16; o; o >>= 1) {
        at += __shfl_xor_sync(0xffffffffu, at, o);
        ap += __shfl_xor_sync(0xffffffffu, ap, o);
    }
    if (lane == 0) {
        st_scr[m] = at + vproj_scr[2*CC];
        sp_scr[m] = ap + vproj_scr[2*CC+1];
    }
}

// ---------------- 3. fused: tf32 proj GEMM (blocks 0..127) + sort (128..131) ----
#define A_STRIDE 36
#define B_STRIDE 136
#define B_OFF    4608

__global__ __launch_bounds__(256) void proj_sort_kernel(
        const float* __restrict__ x, const float* __restrict__ wg,
        const float* __restrict__ bg) {
    __shared__ __align__(16) float smem_f[9216];   // 36 KB

    int tid = threadIdx.x;

    if (blockIdx.x < 128) {
        // ------------------- tf32 GEMM path -------------------
        uint32_t* As = (uint32_t*)smem_f;
        uint32_t* Bs = (uint32_t*)(smem_f + B_OFF);
        int m0 = blockIdx.x * 128;
        int wid = tid >> 5, lane = tid & 31;
        int wm = wid & 3, wn = wid >> 2;          // warp tile: 32m x 64n
        int lp4 = lane >> 2, lm4 = lane & 3;

        float acc[2][8][4];
        #pragma unroll
        for (int mi = 0; mi < 2; mi++)
            #pragma unroll
            for (int nt = 0; nt < 8; nt++)
                #pragma unroll
                for (int q = 0; q < 4; q++) acc[mi][nt][q] = 0.f;

        for (int kc = 0; kc < CC; kc += 32) {
            #pragma unroll
            for (int r = 0; r < 4; r++) {       // A: 128 rows x 32 k
                int idx = tid + r*256;
                int row = idx >> 3, c4 = idx & 7;
                float4 v = *(const float4*)(x + (size_t)(m0+row)*CC + kc + c4*4);
                uint4 t = make_uint4(f2tf32(v.x), f2tf32(v.y), f2tf32(v.z), f2tf32(v.w));
                *(uint4*)&As[row*A_STRIDE + c4*4] = t;
            }
            #pragma unroll
            for (int r = 0; r < 4; r++) {       // B: 32 k-rows x 128 n
                int idx = tid + r*256;
                int row = idx >> 5, c4 = idx & 31;
                float4 v = *(const float4*)(wg + (size_t)(kc+row)*II + c4*4);
                uint4 t = make_uint4(f2tf32(v.x), f2tf32(v.y), f2tf32(v.z), f2tf32(v.w));
                *(uint4*)&Bs[row*B_STRIDE + c4*4] = t;
            }
            __syncthreads();

            #pragma unroll
            for (int k8 = 0; k8 < 32; k8 += 8) {
                uint32_t afr[2][4];
                #pragma unroll
                for (int mi = 0; mi < 2; mi++) {
                    int rb = wm*32 + mi*16;
                    afr[mi][0] = As[(rb + lp4    )*A_STRIDE + k8 + lm4];
                    afr[mi][1] = As[(rb + lp4 + 8)*A_STRIDE + k8 + lm4];
                    afr[mi][2] = As[(rb + lp4    )*A_STRIDE + k8 + 4 + lm4];
                    afr[mi][3] = As[(rb + lp4 + 8)*A_STRIDE + k8 + 4 + lm4];
                }
                #pragma unroll
                for (int nt = 0; nt < 8; nt++) {
                    int nb = wn*64 + nt*8;
                    uint32_t b0 = Bs[(k8 + lm4    )*B_STRIDE + nb + lp4];
                    uint32_t b1 = Bs[(k8 + 4 + lm4)*B_STRIDE + nb + lp4];
                    mma_tf32(acc[0][nt], afr[0], b0, b1);
                    mma_tf32(acc[1][nt], afr[1], b0, b1);
                }
            }
            __syncthreads();
        }
        #pragma unroll
        for (int mi = 0; mi < 2; mi++) {
            #pragma unroll
            for (int nt = 0; nt < 8; nt++) {
                int col = wn*64 + nt*8 + lm4*2;
                float bg0 = __ldg(bg + col), bg1 = __ldg(bg + col + 1);
                int r0 = m0 + wm*32 + mi*16 + lp4;
                float2 v0 = make_float2(acc[mi][nt][0] + bg0, acc[mi][nt][1] + bg1);
                float2 v1 = make_float2(acc[mi][nt][2] + bg0, acc[mi][nt][3] + bg1);
                *(float2*)&g_scr[(size_t)r0*II + col]       = v0;
                *(float2*)&g_scr[(size_t)(r0+8)*II + col]   = v1;
            }
        }
    } else {
        // ------------------- sort path (4 blocks, one per batch) -------------------
        float* k_sm = smem_f;
        int*   i_sm = (int*)(smem_f + NT);
        int b = blockIdx.x - 128;

        int base = tid * 16;
        float kk[16]; int ii[16];
        #pragma unroll
        for (int l = 0; l < 16; l++) { kk[l] = st_scr[b*NT + base + l]; ii[l] = base + l; }
        #pragma unroll
        for (int k2 = 2; k2 <= 16; k2 <<= 1) {
            #pragma unroll
            for (int j2 = k2 >> 1; j2 > 0; j2 >>= 1) {
                #pragma unroll
                for (int p = 0; p < 16; p++) {
                    if (!(p & j2)) {
                        bool up = (((base + p) & k2) == 0);
                        cswap(kk[p], kk[p + j2], ii[p], ii[p + j2], up);
                    }
                }
            }
        }
        #pragma unroll
        for (int l = 0; l < 16; l++) { k_sm[base + l] = kk[l]; i_sm[base + l] = ii[l]; }
        __syncthreads();

        for (int k = 32; k <= NT; k <<= 1) {
            for (int j = k >> 1; j >= 16; j >>= 1) {
                #pragma unroll
                for (int w = 0; w < 8; w++) {
                    int i = tid + w*256;
                    int p = ((i & ~(j - 1)) << 1) | (i & (j - 1));
                    bool up = ((p & k) == 0);
                    float a = k_sm[p], c2 = k_sm[p + j];
                    if ((a > c2) == up) {
                        k_sm[p] = c2; k_sm[p + j] = a;
                        int t0 = i_sm[p]; i_sm[p] = i_sm[p + j]; i_sm[p + j] = t0;
                    }
                }
                __syncthreads();
            }
            bool up = ((base & k) == 0);
            #pragma unroll
            for (int l = 0; l < 16; l++) { kk[l] = k_sm[base + l]; ii[l] = i_sm[base + l]; }
            #pragma unroll
            for (int j2 = 8; j2 > 0; j2 >>= 1) {
                #pragma unroll
                for (int p = 0; p < 16; p++) {
                    if (!(p & j2)) cswap(kk[p], kk[p + j2], ii[p], ii[p + j2], up);
                }
            }
            #pragma unroll
            for (int l = 0; l < 16; l++) { k_sm[base + l] = kk[l]; i_sm[base + l] = ii[l]; }
            __syncthreads();
        }

        #pragma unroll
        for (int w = 0; w < 16; w++) {
            int i = tid + w*256;
            keys_scr[b*NT + i] = k_sm[i];
            perm_scr[b*NT + i] = i_sm[i];
        }
    }
}

// ---------------- 4. chunk sums (512 blocks, CH=32) -----------------------------
__global__ __launch_bounds__(128) void chunk_reduce_kernel() {
    __shared__ int   perm_sm[CH];
    __shared__ float keys_sm[CH];
    int b = blockIdx.x >> 7, c = blockIdx.x & (NCH-1);
    int tid = threadIdx.x;
    int base = b*NT + c*CH;
    if (tid < CH) { perm_sm[tid] = perm_scr[base + tid]; keys_sm[tid] = keys_scr[base + tid]; }
    __syncthreads();
    float a1 = 0.f, a2 = 0.f;
    #pragma unroll 8
    for (int j = 0; j < CH; j++) {
        float g = g_scr[(size_t)(b*NT + perm_sm[j])*II + tid];
        a1 += g;
        a2 += keys_sm[j] * g;
    }
    c12_scr[(size_t)blockIdx.x*II + tid] = make_float2(a1, a2);
}

// ---------------- 5. exclusive suffix over chunk sums + sentinel ----------------
__global__ __launch_bounds__(128) void chunk_suffix_kernel() {
    int b = blockIdx.x, d = threadIdx.x;
    float a1 = 0.f, a2 = 0.f;
    for (int c = NCH - 1; c >= 0; c--) {
        size_t idx = (size_t)(b*NCH + c)*II + d;
        e12_scr[idx] = make_float2(a1, a2);
        float2 v = c12_scr[idx];
        a1 += v.x; a2 += v.y;
    }
    S12_scr[(size_t)(b*(NT+1) + NT)*II + d] = make_float2(0.f, 0.f);
}

// ---------------- 6. fill interleaved suffix-sum table --------------------------
__global__ __launch_bounds__(128) void scan_fill_kernel() {
    __shared__ float g_sm[CH][II];   // 16 KB
    __shared__ int   perm_sm[CH];
    __shared__ float keys_sm[CH];
    int b = blockIdx.x >> 7, c = blockIdx.x & (NCH-1);
    int tid = threadIdx.x;
    int base = b*NT + c*CH;
    if (tid < CH) { perm_sm[tid] = perm_scr[base + tid]; keys_sm[tid] = keys_scr[base + tid]; }
    __syncthreads();
    #pragma unroll 4
    for (int t = 0; t < CH; t++)
        g_sm[t][tid] = g_scr[(size_t)(b*NT + perm_sm[t])*II + tid];
    __syncthreads();
    float2 e = e12_scr[(size_t)(b*NCH + c)*II + tid];
    float a1 = e.x, a2 = e.y;
    for (int j = CH - 1; j >= 0; j--) {
        float g = g_sm[j][tid];
        a1 += g;
        a2 += keys_sm[j] * g;
        int pos = c*CH + j;
        S12_scr[(size_t)(b*(NT+1) + pos)*II + tid] = make_float2(a1, a2);
    }
}

// ---------------- 7. fused final: ypre (search+gather) + tf32 GEMM + BN + res ---
// Block: 128m x 256n (full N), K=128, grid=128, 256 threads, dynamic smem.
// smem floats: keys[4096] | kidx(int)[128] | sp[128] | sc[256] | sh[256]
//              | A tf32 [128][132] | B tf32 [32][264]
#define F_KEYS 0
#define F_KIDX 4096
#define F_SP   4224
#define F_SC   4352
#define F_SH   4608
#define F_A    4864
#define FA_STRIDE 132
#define F_B    (F_A + 128*FA_STRIDE)          // 4864 + 16896 = 21760
#define FB_STRIDE 264
#define F_TOTAL (F_B + 32*FB_STRIDE)          // 21760 + 8448 = 30208 floats
#define F_SMEM_BYTES (F_TOTAL * 4)            // 120832 bytes

__global__ __launch_bounds__(256) void final_mega_kernel(
        const float* __restrict__ x, const float* __restrict__ ww,
        const float* __restrict__ bw, const float* __restrict__ gamma,
        const float* __restrict__ beta, const float* __restrict__ bn_mean,
        const float* __restrict__ bn_var, float* __restrict__ out) {
    extern __shared__ __align__(16) float smem[];
    float*    keys_sm = smem + F_KEYS;
    int*      kidx_sm = (int*)(smem + F_KIDX);
    float*    sp_sm   = smem + F_SP;
    float*    sc_sm   = smem + F_SC;
    float*    sh_sm   = smem + F_SH;
    uint32_t* As      = (uint32_t*)(smem + F_A);
    uint32_t* Bs      = (uint32_t*)(smem + F_B);

    int tid = threadIdx.x;
    int m0  = blockIdx.x * 128;
    int b   = m0 >> 12;                        // batch = m0 / 4096

    // ---- phase 0: load keys, sp, fold BN constants ----
    for (int i = tid; i < NT; i += 256) keys_sm[i] = keys_scr[b*NT + i];
    if (tid < 128) sp_sm[tid] = sp_scr[m0 + tid];
    {
        float sc = gamma[tid] * rsqrtf(bn_var[tid] + BN_EPS);
        sc_sm[tid] = sc;
        sh_sm[tid] = (bw[tid] - bn_mean[tid]) * sc + beta[tid];
    }
    __syncthreads();

    // ---- phase 1a: parallel binary searches (one thread per row) ----
    if (tid < 128) {
        float t = -sp_sm[tid];
        int lo = 0, hi = NT;
        #pragma unroll
        for (int it = 0; it < 12; it++) {
            int mid = (lo + hi) >> 1;
            float kv = (mid < NT) ? keys_sm[mid] : __int_as_float(0x7f800000);
            if (kv > t) hi = mid; else lo = mid + 1;
        }
        kidx_sm[tid] = lo > NT ? NT : lo;
    }
    __syncthreads();

    // ---- phase 1b: gather S12 rows, build A = ypre (tf32) in smem ----
    {
        int h = tid >> 7, l = tid & 127;       // two 128-thread groups, 64 rows each
        const float inv_n = 1.0f / (float)NT;
        #pragma unroll 4
        for (int r = h*64; r < h*64 + 64; r++) {
            int k = kidx_sm[r];
            float2 s = S12_scr[(size_t)(b*(NT+1) + k)*II + l];
            float y = (sp_sm[r]*s.x + s.y) * inv_n;
            As[r*FA_STRIDE + l] = f2tf32(y);
        }
    }
    __syncthreads();

    // ---- phase 2: tf32 GEMM 128x256x128 ----
    int wid = tid >> 5, lane = tid & 31;
    int wm = wid & 3, wn = wid >> 2;           // warp tile: 32m x 128n
    int lp4 = lane >> 2, lm4 = lane & 3;

    float acc[2][16][4];
    #pragma unroll
    for (int mi = 0; mi < 2; mi++)
        #pragma unroll
        for (int nt = 0; nt < 16; nt++)
            #pragma unroll
            for (int q = 0; q < 4; q++) acc[mi][nt][q] = 0.f;

    for (int kc = 0; kc < II; kc += 32) {
        // stage B: 32 k-rows x 256 n (64 float4 per row)
        #pragma unroll
        for (int r = 0; r < 8; r++) {
            int idx = tid + r*256;
            int row = idx >> 6, c4 = idx & 63;
            float4 v = *(const float4*)(ww + (size_t)(kc+row)*CC + c4*4);
            uint4 t = make_uint4(f2tf32(v.x), f2tf32(v.y), f2tf32(v.z), f2tf32(v.w));
            *(uint4*)&Bs[row*FB_STRIDE + c4*4] = t;
        }
        __syncthreads();

        #pragma unroll
        for (int k8 = 0; k8 < 32; k8 += 8) {
            int kA = kc + k8;
            uint32_t afr[2][4];
            #pragma unroll
            for (int mi = 0; mi < 2; mi++) {
                int rb = wm*32 + mi*16;
                afr[mi][0] = As[(rb + lp4    )*FA_STRIDE + kA + lm4];
                afr[mi][1] = As[(rb + lp4 + 8)*FA_STRIDE + kA + lm4];
                afr[mi][2] = As[(rb + lp4    )*FA_STRIDE + kA + 4 + lm4];
                afr[mi][3] = As[(rb + lp4 + 8)*FA_STRIDE + kA + 4 + lm4];
            }
            #pragma unroll
            for (int nt = 0; nt < 16; nt++) {
                int nb = wn*128 + nt*8;
                uint32_t b0 = Bs[(k8 + lm4    )*FB_STRIDE + nb + lp4];
                uint32_t b1 = Bs[(k8 + 4 + lm4)*FB_STRIDE + nb + lp4];
                mma_tf32(acc[0][nt], afr[0], b0, b1);
                mma_tf32(acc[1][nt], afr[1], b0, b1);
            }
        }
        __syncthreads();
    }

    // ---- epilogue: BN scale/shift + residual ----
    #pragma unroll
    for (int mi = 0; mi < 2; mi++) {
        #pragma unroll
        for (int nt = 0; nt < 16; nt++) {
            int col = wn*128 + nt*8 + lm4*2;
            float s0 = sc_sm[col], s1 = sc_sm[col+1];
            float h0 = sh_sm[col], h1 = sh_sm[col+1];
            int r0 = m0 + wm*32 + mi*16 + lp4;
            float2 x0 = *(const float2*)(x + (size_t)r0*CC + col);
            float2 x1 = *(const float2*)(x + (size_t)(r0+8)*CC + col);
            float2 v0 = make_float2(acc[mi][nt][0]*s0 + h0 + x0.x,
                                    acc[mi][nt][1]*s1 + h1 + x0.y);
            float2 v1 = make_float2(acc[mi][nt][2]*s0 + h0 + x1.x,
                                    acc[mi][nt][3]*s1 + h1 + x1.y);
            *(float2*)(out + (size_t)r0*CC + col)     = v0;
            *(float2*)(out + (size_t)(r0+8)*CC + col) = v1;
        }
    }
}

// ---------------- launch ---------------------------------------------------------
extern "C" void kernel_launch(void* const* d_in, const int* in_sizes, int n_in,
                              void* d_out, int out_size) {
    const float* x     = (const float*)d_in[0];
    const float* wg    = (const float*)d_in[1];
    const float* bg    = (const float*)d_in[2];
    const float* wt    = (const float*)d_in[3];
    const float* bt    = (const float*)d_in[4];
    const float* wp    = (const float*)d_in[5];
    const float* bp    = (const float*)d_in[6];
    const float* wc    = (const float*)d_in[7];
    const float* ww    = (const float*)d_in[8];
    const float* bw    = (const float*)d_in[9];
    const float* gamma = (const float*)d_in[10];
    const float* beta  = (const float*)d_in[11];
    const float* bmean = (const float*)d_in[12];
    const float* bvar  = (const float*)d_in[13];
    float* out = (float*)d_out;

    static bool attr_set = false;
    if (!attr_set) {
        cudaFuncSetAttribute(final_mega_kernel,
                             cudaFuncAttributeMaxDynamicSharedMemorySize,
                             F_SMEM_BYTES);
        attr_set = true;
    }

    prep_kernel<<<1, 256>>>(wt, bt, wp, bp, wc);
    scores_kernel<<<(BB*NT)/8, 256>>>(x);
    proj_sort_kernel<<<128 + BB, 256>>>(x, wg, bg);
    chunk_reduce_kernel<<<BB*NCH, 128>>>();
    chunk_suffix_kernel<<<BB, 128>>>();
    scan_fill_kernel<<<BB*NCH, 128>>>();
    final_mega_kernel<<<128, 256, F_SMEM_BYTES>>>(
        x, ww, bw, gamma, beta, bmean, bvar, out);
}